// round 11
// baseline (speedup 1.0000x reference)
#include <cuda_runtime.h>
#include <cuda_fp16.h>
#include <cstdint>

#define B_SAMPLES 32768
#define N_CLASSES 10
#define UNIT 16
#define D_IN 160
#define D_IN_PAD 192
#define H1_DIM 512
#define H2_DIM 1024
#define O_DIM 3072

// ---------------- scratch ----------------
__device__ __align__(128) __half g_vj[(size_t)B_SAMPLES * D_IN_PAD];
__device__ __align__(128) __half g_h1[(size_t)B_SAMPLES * H1_DIM];
__device__ __align__(128) __half g_h2[(size_t)B_SAMPLES * H2_DIM];
__device__ __align__(128) __half g_w1[(size_t)D_IN * H1_DIM];
__device__ __align__(128) __half g_w2[(size_t)H1_DIM * H2_DIM];
__device__ __align__(128) __half g_w3[(size_t)H2_DIM * O_DIM];

#define W1_N2 (D_IN * H1_DIM / 2)
#define W2_N2 (H1_DIM * H2_DIM / 2)
#define W3_N2 (H2_DIM * O_DIM / 2)

// ---------------- merged fp32 -> fp16 ----------------
__global__ void f2h_all(const float2* __restrict__ w1,
                        const float2* __restrict__ w2,
                        const float2* __restrict__ w3,
                        __half2* __restrict__ o1,
                        __half2* __restrict__ o2,
                        __half2* __restrict__ o3) {
    const int total = W1_N2 + W2_N2 + W3_N2;
    int i = blockIdx.x * blockDim.x + threadIdx.x;
    int stride = gridDim.x * blockDim.x;
    for (; i < total; i += stride) {
        float2 v;
        __half2* dst;
        if (i < W1_N2) {
            v = w1[i];
            dst = o1 + i;
        } else if (i < W1_N2 + W2_N2) {
            v = w2[i - W1_N2];
            dst = o2 + (i - W1_N2);
        } else {
            v = w3[i - W1_N2 - W2_N2];
            dst = o3 + (i - W1_N2 - W2_N2);
        }
        *dst = __floats2half2_rn(v.x, v.y);
    }
}

// ---------------- capsule mask -> vj padded to 192 cols ---------------------
__global__ __launch_bounds__(256) void mask_kernel(const float* __restrict__ x,
                                                   __half* __restrict__ vj) {
    __shared__ float xs[64 * 168];
    __shared__ int bi[64];
    const int b0 = blockIdx.x * 64;

    const float4* src = (const float4*)(x + (size_t)b0 * D_IN);
    for (int q = threadIdx.x; q < 64 * 40; q += 256) {
        int s = q / 40, f = q % 40;
        *(float4*)&xs[s * 168 + f * 4] = src[q];
    }
    __syncthreads();

    if (threadIdx.x < 64) {
        const float* r = &xs[threadIdx.x * 168];
        float best = -1.f;
        int bidx = 0;
#pragma unroll
        for (int c = 0; c < N_CLASSES; c++) {
            float s = 0.f;
#pragma unroll
            for (int j = 0; j < UNIT; j++) {
                float v = r[c * UNIT + j];
                s += v * v;
            }
            if (s > best) { best = s; bidx = c; }
        }
        bi[threadIdx.x] = bidx;
    }
    __syncthreads();

    uint4* dst = (uint4*)(vj + (size_t)b0 * D_IN_PAD);
    for (int q = threadIdx.x; q < 64 * 24; q += 256) {
        int s = q / 24, j = q % 24;
        uint4 v = make_uint4(0u, 0u, 0u, 0u);
        int c = j >> 1;
        if (j < 20 && c == bi[s]) {
            const float* p = &xs[s * 168 + c * UNIT + (j & 1) * 8];
            __half2 h0 = __floats2half2_rn(p[0], p[1]);
            __half2 h1 = __floats2half2_rn(p[2], p[3]);
            __half2 h2 = __floats2half2_rn(p[4], p[5]);
            __half2 h3 = __floats2half2_rn(p[6], p[7]);
            v.x = *(uint32_t*)&h0; v.y = *(uint32_t*)&h1;
            v.z = *(uint32_t*)&h2; v.w = *(uint32_t*)&h3;
        }
        dst[q] = v;
    }
}

// ---------------- mma helpers ----------------
__device__ __forceinline__ void ldm_x4(uint32_t& r0, uint32_t& r1,
                                       uint32_t& r2, uint32_t& r3,
                                       uint32_t addr) {
    asm volatile("ldmatrix.sync.aligned.m8n8.x4.shared.b16 {%0,%1,%2,%3}, [%4];\n"
                 : "=r"(r0), "=r"(r1), "=r"(r2), "=r"(r3)
                 : "r"(addr));
}

__device__ __forceinline__ void ldm_x4_t(uint32_t& r0, uint32_t& r1,
                                         uint32_t& r2, uint32_t& r3,
                                         uint32_t addr) {
    asm volatile("ldmatrix.sync.aligned.m8n8.x4.trans.shared.b16 {%0,%1,%2,%3}, [%4];\n"
                 : "=r"(r0), "=r"(r1), "=r"(r2), "=r"(r3)
                 : "r"(addr));
}

__device__ __forceinline__ void mma_f16(uint32_t* c, const uint32_t* a,
                                        const uint32_t* b) {
    asm volatile(
        "mma.sync.aligned.m16n8k16.row.col.f16.f16.f16.f16 "
        "{%0,%1}, {%2,%3,%4,%5}, {%6,%7}, {%0,%1};\n"
        : "+r"(c[0]), "+r"(c[1])
        : "r"(a[0]), "r"(a[1]), "r"(a[2]), "r"(a[3]), "r"(b[0]), "r"(b[1]));
}

// ---------------- geometry: BM=128, BN=512, BK=64, 2 stages, 1 CTA/SM -------
#define BK 64
#define A_LDS 72     // 64 + 8 (halves)
#define B_LDS 520    // 512 + 8 (halves)
#define STAGES 2
#define A_STG (128 * A_LDS)          // 9216 halves
#define B_STG (BK * B_LDS)           // 33280 halves
#define SMEM_BYTES (STAGES * (A_STG + B_STG) * 2)   // 169984 B

// A tile 128x64 (1024 x 16B -> 4/thr), B tile 64x512 (4096 x 16B -> 16/thr)
__device__ __forceinline__ void ld_stage(uint32_t sA, uint32_t sB,
                                         const __half* __restrict__ A,
                                         const __half* __restrict__ Bm,
                                         int bm, int bn, int K, int N, int t,
                                         int tid) {
    const __half* Ag = A + (size_t)bm * K + t * BK;
    const __half* Bg = Bm + (size_t)t * BK * N + bn;
#pragma unroll
    for (int i = 0; i < 4; i++) {
        int q = tid + i * 256;
        int ar = q >> 3, ac = (q & 7) * 8;
        asm volatile("cp.async.cg.shared.global [%0], [%1], 16;" ::
                     "r"(sA + (uint32_t)(ar * A_LDS + ac) * 2u),
                     "l"(Ag + (size_t)ar * K + ac));
    }
#pragma unroll
    for (int i = 0; i < 16; i++) {
        int q = tid + i * 256;
        int br = q >> 6, bc = (q & 63) * 8;
        asm volatile("cp.async.cg.shared.global [%0], [%1], 16;" ::
                     "r"(sB + (uint32_t)(br * B_LDS + bc) * 2u),
                     "l"(Bg + (size_t)br * N + bc));
    }
    asm volatile("cp.async.commit_group;" ::: "memory");
}

// ================= GEMM: tile 128x512, warp tile 64x128 =================
// 8 warps (2 warpM x 4 warpN). fp16 accumulation. 1 CTA/SM.
template <int ACT>
__global__ __launch_bounds__(256, 1) void gemm_kernel(
    const __half* __restrict__ A,
    const __half* __restrict__ Bm,
    const float* __restrict__ bias,
    void* __restrict__ Cout,
    int N, int K) {
    extern __shared__ __half smem[];

    const int tid = threadIdx.x;
    const int warp = tid >> 5;
    const int lane = tid & 31;
    const int warpM = warp >> 2;
    const int warpN = warp & 3;
    const int bm = blockIdx.y * 128;
    const int bn = blockIdx.x * 512;

    const uint32_t sBase = (uint32_t)__cvta_generic_to_shared(smem);
    const uint32_t aBase = sBase;
    const uint32_t bBase = sBase + (uint32_t)STAGES * A_STG * 2u;

    uint32_t acc[4][16][2];
#pragma unroll
    for (int mt = 0; mt < 4; mt++)
#pragma unroll
        for (int n8 = 0; n8 < 16; n8++) {
            acc[mt][n8][0] = 0u;
            acc[mt][n8][1] = 0u;
        }

    const int T = K / BK;

    ld_stage(aBase, bBase, A, Bm, bm, bn, K, N, 0, tid);

    for (int t = 0; t < T; t++) {
        if (t + 1 < T) {
            int sl = (t + 1) & 1;
            ld_stage(aBase + (uint32_t)sl * A_STG * 2u,
                     bBase + (uint32_t)sl * B_STG * 2u,
                     A, Bm, bm, bn, K, N, t + 1, tid);
        } else {
            asm volatile("cp.async.commit_group;" ::: "memory");
        }
        asm volatile("cp.async.wait_group 1;" ::: "memory");
        __syncthreads();

        const int s = t & 1;
        const uint32_t sA = aBase + (uint32_t)s * A_STG * 2u;
        const uint32_t sB = bBase + (uint32_t)s * B_STG * 2u;

#pragma unroll
        for (int kk = 0; kk < BK; kk += 16) {
            uint32_t a[4][4];
#pragma unroll
            for (int mt = 0; mt < 4; mt++) {
                int row = warpM * 64 + mt * 16 + (lane & 15);
                int col = kk + ((lane >> 4) << 3);
                ldm_x4(a[mt][0], a[mt][1], a[mt][2], a[mt][3],
                       sA + (uint32_t)(row * A_LDS + col) * 2u);
            }
            // two halves of the 128-wide N range to ease register pressure
#pragma unroll
            for (int h = 0; h < 2; h++) {
                uint32_t b[8][2];
#pragma unroll
                for (int nt = 0; nt < 4; nt++) {
                    int row = kk + (lane & 15);
                    int col = warpN * 128 + h * 64 + nt * 16 + ((lane >> 4) << 3);
                    uint32_t r0, r1, r2, r3;
                    ldm_x4_t(r0, r1, r2, r3,
                             sB + (uint32_t)(row * B_LDS + col) * 2u);
                    b[2 * nt][0] = r0; b[2 * nt][1] = r1;
                    b[2 * nt + 1][0] = r2; b[2 * nt + 1][1] = r3;
                }
#pragma unroll
                for (int mt = 0; mt < 4; mt++)
#pragma unroll
                    for (int nb = 0; nb < 8; nb++)
                        mma_f16(acc[mt][h * 8 + nb], a[mt], b[nb]);
            }
        }
        __syncthreads();
    }

    // epilogue
    const int lr = lane >> 2;
    const int lc = (lane & 3) * 2;
#pragma unroll
    for (int mt = 0; mt < 4; mt++) {
#pragma unroll
        for (int n8 = 0; n8 < 16; n8++) {
            int row0 = bm + warpM * 64 + mt * 16 + lr;
            int col = bn + warpN * 128 + n8 * 8 + lc;
            float bz0 = __ldg(bias + col);
            float bz1 = __ldg(bias + col + 1);
            float2 p0 = __half22float2(*(__half2*)&acc[mt][n8][0]);
            float2 p1 = __half22float2(*(__half2*)&acc[mt][n8][1]);
            float v00 = p0.x + bz0;
            float v01 = p0.y + bz1;
            float v10 = p1.x + bz0;
            float v11 = p1.y + bz1;
            if (ACT == 0) {
                v00 = fmaxf(v00, 0.f); v01 = fmaxf(v01, 0.f);
                v10 = fmaxf(v10, 0.f); v11 = fmaxf(v11, 0.f);
                __half* C = (__half*)Cout;
                *(__half2*)&C[(size_t)row0 * N + col] = __floats2half2_rn(v00, v01);
                *(__half2*)&C[(size_t)(row0 + 8) * N + col] = __floats2half2_rn(v10, v11);
            } else {
                v00 = 1.f / (1.f + __expf(-v00));
                v01 = 1.f / (1.f + __expf(-v01));
                v10 = 1.f / (1.f + __expf(-v10));
                v11 = 1.f / (1.f + __expf(-v11));
                float* C = (float*)Cout;
                *(float2*)&C[(size_t)row0 * N + col] = make_float2(v00, v01);
                *(float2*)&C[(size_t)(row0 + 8) * N + col] = make_float2(v10, v11);
            }
        }
    }
}

// ---------------- launch ----------------
extern "C" void kernel_launch(void* const* d_in, const int* in_sizes, int n_in,
                              void* d_out, int out_size) {
    const float* x  = (const float*)d_in[0];
    const float* W1 = (const float*)d_in[2];
    const float* b1 = (const float*)d_in[3];
    const float* W2 = (const float*)d_in[4];
    const float* b2 = (const float*)d_in[5];
    const float* W3 = (const float*)d_in[6];
    const float* b3 = (const float*)d_in[7];

    void *pvj, *ph1, *ph2, *pw1, *pw2, *pw3;
    cudaGetSymbolAddress(&pvj, g_vj);
    cudaGetSymbolAddress(&ph1, g_h1);
    cudaGetSymbolAddress(&ph2, g_h2);
    cudaGetSymbolAddress(&pw1, g_w1);
    cudaGetSymbolAddress(&pw2, g_w2);
    cudaGetSymbolAddress(&pw3, g_w3);
    __half* vj  = (__half*)pvj;
    __half* h1  = (__half*)ph1;
    __half* h2  = (__half*)ph2;
    __half* w1h = (__half*)pw1;
    __half* w2h = (__half*)pw2;
    __half* w3h = (__half*)pw3;

    cudaFuncSetAttribute(gemm_kernel<0>,
                         cudaFuncAttributeMaxDynamicSharedMemorySize, SMEM_BYTES);
    cudaFuncSetAttribute(gemm_kernel<1>,
                         cudaFuncAttributeMaxDynamicSharedMemorySize, SMEM_BYTES);

    f2h_all<<<592, 256>>>((const float2*)W1, (const float2*)W2,
                          (const float2*)W3, (__half2*)w1h,
                          (__half2*)w2h, (__half2*)w3h);

    mask_kernel<<<B_SAMPLES / 64, 256>>>(x, vj);

    gemm_kernel<0><<<dim3(H1_DIM / 512, B_SAMPLES / 128), 256, SMEM_BYTES>>>(
        vj, w1h, b1, h1, H1_DIM, D_IN_PAD);
    gemm_kernel<0><<<dim3(H2_DIM / 512, B_SAMPLES / 128), 256, SMEM_BYTES>>>(
        h1, w2h, b2, h2, H2_DIM, H1_DIM);
    gemm_kernel<1><<<dim3(O_DIM / 512, B_SAMPLES / 128), 256, SMEM_BYTES>>>(
        h2, w3h, b3, d_out, O_DIM, H2_DIM);
}

// round 12
// speedup vs baseline: 1.3300x; 1.3300x over previous
#include <cuda_runtime.h>
#include <cuda_fp16.h>
#include <cstdint>

#define B_SAMPLES 32768
#define N_CLASSES 10
#define UNIT 16
#define D_IN 160
#define D_IN_PAD 192
#define H1_DIM 512
#define H2_DIM 1024
#define O_DIM 3072

// ---------------- scratch ----------------
__device__ __align__(128) __half g_vj[(size_t)B_SAMPLES * D_IN_PAD];
__device__ __align__(128) __half g_h1[(size_t)B_SAMPLES * H1_DIM];
__device__ __align__(128) __half g_h2[(size_t)B_SAMPLES * H2_DIM];
__device__ __align__(128) __half g_w1[(size_t)D_IN * H1_DIM];
__device__ __align__(128) __half g_w2[(size_t)H1_DIM * H2_DIM];
__device__ __align__(128) __half g_w3[(size_t)H2_DIM * O_DIM];

#define W1_N2 (D_IN * H1_DIM / 2)
#define W2_N2 (H1_DIM * H2_DIM / 2)
#define W3_N2 (H2_DIM * O_DIM / 2)

// ---------------- merged fp32 -> fp16 ----------------
__global__ void f2h_all(const float2* __restrict__ w1,
                        const float2* __restrict__ w2,
                        const float2* __restrict__ w3,
                        __half2* __restrict__ o1,
                        __half2* __restrict__ o2,
                        __half2* __restrict__ o3) {
    const int total = W1_N2 + W2_N2 + W3_N2;
    int i = blockIdx.x * blockDim.x + threadIdx.x;
    int stride = gridDim.x * blockDim.x;
    for (; i < total; i += stride) {
        float2 v;
        __half2* dst;
        if (i < W1_N2) {
            v = w1[i];
            dst = o1 + i;
        } else if (i < W1_N2 + W2_N2) {
            v = w2[i - W1_N2];
            dst = o2 + (i - W1_N2);
        } else {
            v = w3[i - W1_N2 - W2_N2];
            dst = o3 + (i - W1_N2 - W2_N2);
        }
        *dst = __floats2half2_rn(v.x, v.y);
    }
}

// ---------------- capsule mask -> vj padded to 192 cols ---------------------
__global__ __launch_bounds__(256) void mask_kernel(const float* __restrict__ x,
                                                   __half* __restrict__ vj) {
    __shared__ float xs[64 * 168];
    __shared__ int bi[64];
    const int b0 = blockIdx.x * 64;

    const float4* src = (const float4*)(x + (size_t)b0 * D_IN);
    for (int q = threadIdx.x; q < 64 * 40; q += 256) {
        int s = q / 40, f = q % 40;
        *(float4*)&xs[s * 168 + f * 4] = src[q];
    }
    __syncthreads();

    if (threadIdx.x < 64) {
        const float* r = &xs[threadIdx.x * 168];
        float best = -1.f;
        int bidx = 0;
#pragma unroll
        for (int c = 0; c < N_CLASSES; c++) {
            float s = 0.f;
#pragma unroll
            for (int j = 0; j < UNIT; j++) {
                float v = r[c * UNIT + j];
                s += v * v;
            }
            if (s > best) { best = s; bidx = c; }
        }
        bi[threadIdx.x] = bidx;
    }
    __syncthreads();

    uint4* dst = (uint4*)(vj + (size_t)b0 * D_IN_PAD);
    for (int q = threadIdx.x; q < 64 * 24; q += 256) {
        int s = q / 24, j = q % 24;
        uint4 v = make_uint4(0u, 0u, 0u, 0u);
        int c = j >> 1;
        if (j < 20 && c == bi[s]) {
            const float* p = &xs[s * 168 + c * UNIT + (j & 1) * 8];
            __half2 h0 = __floats2half2_rn(p[0], p[1]);
            __half2 h1 = __floats2half2_rn(p[2], p[3]);
            __half2 h2 = __floats2half2_rn(p[4], p[5]);
            __half2 h3 = __floats2half2_rn(p[6], p[7]);
            v.x = *(uint32_t*)&h0; v.y = *(uint32_t*)&h1;
            v.z = *(uint32_t*)&h2; v.w = *(uint32_t*)&h3;
        }
        dst[q] = v;
    }
}

// ---------------- mma helpers ----------------
__device__ __forceinline__ void ldm_x4(uint32_t& r0, uint32_t& r1,
                                       uint32_t& r2, uint32_t& r3,
                                       uint32_t addr) {
    asm volatile("ldmatrix.sync.aligned.m8n8.x4.shared.b16 {%0,%1,%2,%3}, [%4];\n"
                 : "=r"(r0), "=r"(r1), "=r"(r2), "=r"(r3)
                 : "r"(addr));
}

__device__ __forceinline__ void ldm_x4_t(uint32_t& r0, uint32_t& r1,
                                         uint32_t& r2, uint32_t& r3,
                                         uint32_t addr) {
    asm volatile("ldmatrix.sync.aligned.m8n8.x4.trans.shared.b16 {%0,%1,%2,%3}, [%4];\n"
                 : "=r"(r0), "=r"(r1), "=r"(r2), "=r"(r3)
                 : "r"(addr));
}

__device__ __forceinline__ void mma_f16(uint32_t* c, const uint32_t* a,
                                        const uint32_t* b) {
    asm volatile(
        "mma.sync.aligned.m16n8k16.row.col.f16.f16.f16.f16 "
        "{%0,%1}, {%2,%3,%4,%5}, {%6,%7}, {%0,%1};\n"
        : "+r"(c[0]), "+r"(c[1])
        : "r"(a[0]), "r"(a[1]), "r"(a[2]), "r"(a[3]), "r"(b[0]), "r"(b[1]));
}

// ---------------- geometry: BM=128, BN=256, BK=64, 2 stages ----------------
#define BK 64
#define A_LDS 72     // 64 + 8 (halves)
#define B_LDS 264    // 256 + 8 (halves)
#define STAGES 2
#define A_STG (128 * A_LDS)          // 9216 halves
#define B_STG (BK * B_LDS)           // 16896 halves
#define SMEM_BYTES (STAGES * (A_STG + B_STG) * 2)   // 104448 B

__device__ __forceinline__ void ld_stage(uint32_t sA, uint32_t sB,
                                         const __half* __restrict__ A,
                                         const __half* __restrict__ Bm,
                                         int bm, int bn, int K, int N, int t,
                                         int tid) {
    const __half* Ag = A + (size_t)bm * K + t * BK;
    const __half* Bg = Bm + (size_t)t * BK * N + bn;
#pragma unroll
    for (int i = 0; i < 4; i++) {
        int q = tid + i * 256;
        int ar = q >> 3, ac = (q & 7) * 8;
        asm volatile("cp.async.cg.shared.global [%0], [%1], 16;" ::
                     "r"(sA + (uint32_t)(ar * A_LDS + ac) * 2u),
                     "l"(Ag + (size_t)ar * K + ac));
    }
#pragma unroll
    for (int i = 0; i < 8; i++) {
        int q = tid + i * 256;
        int br = q >> 5, bc = (q & 31) * 8;
        asm volatile("cp.async.cg.shared.global [%0], [%1], 16;" ::
                     "r"(sB + (uint32_t)(br * B_LDS + bc) * 2u),
                     "l"(Bg + (size_t)br * N + bc));
    }
    asm volatile("cp.async.commit_group;" ::: "memory");
}

// ================= GEMM: tile 128x256, warp tile 64x64, A-frag pipelined ====
template <int ACT>
__global__ __launch_bounds__(256, 2) void gemm_kernel(
    const __half* __restrict__ A,
    const __half* __restrict__ Bm,
    const float* __restrict__ bias,
    void* __restrict__ Cout,
    int N, int K) {
    extern __shared__ __half smem[];

    const int tid = threadIdx.x;
    const int warp = tid >> 5;
    const int lane = tid & 31;
    const int warpM = warp >> 2;
    const int warpN = warp & 3;
    const int bm = blockIdx.y * 128;
    const int bn = blockIdx.x * 256;

    const uint32_t sBase = (uint32_t)__cvta_generic_to_shared(smem);
    const uint32_t aBase = sBase;
    const uint32_t bBase = sBase + (uint32_t)STAGES * A_STG * 2u;

    // loop-invariant LDSM address offsets (bytes) within a stage
    const uint32_t aOffBase =
        (uint32_t)((warpM * 64 + (lane & 15)) * A_LDS + ((lane >> 4) << 3)) * 2u;
    const uint32_t bOffBase =
        (uint32_t)((lane & 15) * B_LDS + warpN * 64 + ((lane >> 4) << 3)) * 2u;

    uint32_t acc[4][8][2];
#pragma unroll
    for (int mt = 0; mt < 4; mt++)
#pragma unroll
        for (int n8 = 0; n8 < 8; n8++) {
            acc[mt][n8][0] = 0u;
            acc[mt][n8][1] = 0u;
        }

    const int T = K / BK;

    ld_stage(aBase, bBase, A, Bm, bm, bn, K, N, 0, tid);

    for (int t = 0; t < T; t++) {
        if (t + 1 < T) {
            int sl = (t + 1) & 1;
            ld_stage(aBase + (uint32_t)sl * A_STG * 2u,
                     bBase + (uint32_t)sl * B_STG * 2u,
                     A, Bm, bm, bn, K, N, t + 1, tid);
        } else {
            asm volatile("cp.async.commit_group;" ::: "memory");
        }
        asm volatile("cp.async.wait_group 1;" ::: "memory");
        __syncthreads();

        const int s = t & 1;
        const uint32_t sA = aBase + (uint32_t)s * A_STG * 2u + aOffBase;
        const uint32_t sB = bBase + (uint32_t)s * B_STG * 2u + bOffBase;

        // A-fragment double buffer: preload kk=0
        uint32_t a[2][4][4];
#pragma unroll
        for (int mt = 0; mt < 4; mt++)
            ldm_x4(a[0][mt][0], a[0][mt][1], a[0][mt][2], a[0][mt][3],
                   sA + (uint32_t)(mt * 16 * A_LDS) * 2u);

#pragma unroll
        for (int kk = 0; kk < 4; kk++) {       // 4 chunks of k=16
            // issue B loads for this chunk
            uint32_t b[8][2];
#pragma unroll
            for (int nt = 0; nt < 4; nt++) {
                uint32_t r0, r1, r2, r3;
                ldm_x4_t(r0, r1, r2, r3,
                         sB + (uint32_t)(kk * 16 * B_LDS + nt * 16) * 2u);
                b[2 * nt][0] = r0; b[2 * nt][1] = r1;
                b[2 * nt + 1][0] = r2; b[2 * nt + 1][1] = r3;
            }
            // prefetch A fragments for next chunk (covers b latency)
            if (kk < 3) {
#pragma unroll
                for (int mt = 0; mt < 4; mt++)
                    ldm_x4(a[(kk + 1) & 1][mt][0], a[(kk + 1) & 1][mt][1],
                           a[(kk + 1) & 1][mt][2], a[(kk + 1) & 1][mt][3],
                           sA + (uint32_t)(mt * 16 * A_LDS + (kk + 1) * 16) * 2u);
            }
#pragma unroll
            for (int mt = 0; mt < 4; mt++)
#pragma unroll
                for (int n8 = 0; n8 < 8; n8++)
                    mma_f16(acc[mt][n8], a[kk & 1][mt], b[n8]);
        }
        __syncthreads();
    }

    // epilogue
    const int lr = lane >> 2;
    const int lc = (lane & 3) * 2;
#pragma unroll
    for (int mt = 0; mt < 4; mt++) {
#pragma unroll
        for (int n8 = 0; n8 < 8; n8++) {
            int row0 = bm + warpM * 64 + mt * 16 + lr;
            int col = bn + warpN * 64 + n8 * 8 + lc;
            float bz0 = __ldg(bias + col);
            float bz1 = __ldg(bias + col + 1);
            float2 p0 = __half22float2(*(__half2*)&acc[mt][n8][0]);
            float2 p1 = __half22float2(*(__half2*)&acc[mt][n8][1]);
            float v00 = p0.x + bz0;
            float v01 = p0.y + bz1;
            float v10 = p1.x + bz0;
            float v11 = p1.y + bz1;
            if (ACT == 0) {
                v00 = fmaxf(v00, 0.f); v01 = fmaxf(v01, 0.f);
                v10 = fmaxf(v10, 0.f); v11 = fmaxf(v11, 0.f);
                __half* C = (__half*)Cout;
                *(__half2*)&C[(size_t)row0 * N + col] = __floats2half2_rn(v00, v01);
                *(__half2*)&C[(size_t)(row0 + 8) * N + col] = __floats2half2_rn(v10, v11);
            } else {
                v00 = 1.f / (1.f + __expf(-v00));
                v01 = 1.f / (1.f + __expf(-v01));
                v10 = 1.f / (1.f + __expf(-v10));
                v11 = 1.f / (1.f + __expf(-v11));
                float* C = (float*)Cout;
                *(float2*)&C[(size_t)row0 * N + col] = make_float2(v00, v01);
                *(float2*)&C[(size_t)(row0 + 8) * N + col] = make_float2(v10, v11);
            }
        }
    }
}

// ---------------- launch ----------------
extern "C" void kernel_launch(void* const* d_in, const int* in_sizes, int n_in,
                              void* d_out, int out_size) {
    const float* x  = (const float*)d_in[0];
    const float* W1 = (const float*)d_in[2];
    const float* b1 = (const float*)d_in[3];
    const float* W2 = (const float*)d_in[4];
    const float* b2 = (const float*)d_in[5];
    const float* W3 = (const float*)d_in[6];
    const float* b3 = (const float*)d_in[7];

    void *pvj, *ph1, *ph2, *pw1, *pw2, *pw3;
    cudaGetSymbolAddress(&pvj, g_vj);
    cudaGetSymbolAddress(&ph1, g_h1);
    cudaGetSymbolAddress(&ph2, g_h2);
    cudaGetSymbolAddress(&pw1, g_w1);
    cudaGetSymbolAddress(&pw2, g_w2);
    cudaGetSymbolAddress(&pw3, g_w3);
    __half* vj  = (__half*)pvj;
    __half* h1  = (__half*)ph1;
    __half* h2  = (__half*)ph2;
    __half* w1h = (__half*)pw1;
    __half* w2h = (__half*)pw2;
    __half* w3h = (__half*)pw3;

    cudaFuncSetAttribute(gemm_kernel<0>,
                         cudaFuncAttributeMaxDynamicSharedMemorySize, SMEM_BYTES);
    cudaFuncSetAttribute(gemm_kernel<1>,
                         cudaFuncAttributeMaxDynamicSharedMemorySize, SMEM_BYTES);

    f2h_all<<<592, 256>>>((const float2*)W1, (const float2*)W2,
                          (const float2*)W3, (__half2*)w1h,
                          (__half2*)w2h, (__half2*)w3h);

    mask_kernel<<<B_SAMPLES / 64, 256>>>(x, vj);

    gemm_kernel<0><<<dim3(H1_DIM / 256, B_SAMPLES / 128), 256, SMEM_BYTES>>>(
        vj, w1h, b1, h1, H1_DIM, D_IN_PAD);
    gemm_kernel<0><<<dim3(H2_DIM / 256, B_SAMPLES / 128), 256, SMEM_BYTES>>>(
        h1, w2h, b2, h2, H2_DIM, H1_DIM);
    gemm_kernel<1><<<dim3(O_DIM / 256, B_SAMPLES / 128), 256, SMEM_BYTES>>>(
        h2, w3h, b3, d_out, O_DIM, H2_DIM);
}

// round 13
// speedup vs baseline: 1.4249x; 1.0714x over previous
#include <cuda_runtime.h>
#include <cuda_fp16.h>
#include <cstdint>

#define B_SAMPLES 32768
#define N_CLASSES 10
#define UNIT 16
#define D_IN 160
#define D_IN_PAD 192
#define H1_DIM 512
#define H2_DIM 1024
#define O_DIM 3072

// ---------------- scratch ----------------
__device__ __align__(128) __half g_vj[(size_t)B_SAMPLES * D_IN_PAD];
__device__ __align__(128) __half g_h1[(size_t)B_SAMPLES * H1_DIM];
__device__ __align__(128) __half g_h2[(size_t)B_SAMPLES * H2_DIM];
__device__ __align__(128) __half g_w1[(size_t)D_IN * H1_DIM];
__device__ __align__(128) __half g_w2[(size_t)H1_DIM * H2_DIM];
__device__ __align__(128) __half g_w3[(size_t)H2_DIM * O_DIM];

#define W1_N2 (D_IN * H1_DIM / 2)
#define W2_N2 (H1_DIM * H2_DIM / 2)
#define W3_N2 (H2_DIM * O_DIM / 2)

// ---------------- merged fp32 -> fp16 ----------------
__global__ void f2h_all(const float2* __restrict__ w1,
                        const float2* __restrict__ w2,
                        const float2* __restrict__ w3,
                        __half2* __restrict__ o1,
                        __half2* __restrict__ o2,
                        __half2* __restrict__ o3) {
    const int total = W1_N2 + W2_N2 + W3_N2;
    int i = blockIdx.x * blockDim.x + threadIdx.x;
    int stride = gridDim.x * blockDim.x;
    for (; i < total; i += stride) {
        float2 v;
        __half2* dst;
        if (i < W1_N2) {
            v = w1[i];
            dst = o1 + i;
        } else if (i < W1_N2 + W2_N2) {
            v = w2[i - W1_N2];
            dst = o2 + (i - W1_N2);
        } else {
            v = w3[i - W1_N2 - W2_N2];
            dst = o3 + (i - W1_N2 - W2_N2);
        }
        *dst = __floats2half2_rn(v.x, v.y);
    }
}

// ---------------- capsule mask -> vj padded to 192 cols ---------------------
__global__ __launch_bounds__(256) void mask_kernel(const float* __restrict__ x,
                                                   __half* __restrict__ vj) {
    __shared__ float xs[64 * 168];
    __shared__ int bi[64];
    const int b0 = blockIdx.x * 64;

    const float4* src = (const float4*)(x + (size_t)b0 * D_IN);
    for (int q = threadIdx.x; q < 64 * 40; q += 256) {
        int s = q / 40, f = q % 40;
        *(float4*)&xs[s * 168 + f * 4] = src[q];
    }
    __syncthreads();

    if (threadIdx.x < 64) {
        const float* r = &xs[threadIdx.x * 168];
        float best = -1.f;
        int bidx = 0;
#pragma unroll
        for (int c = 0; c < N_CLASSES; c++) {
            float s = 0.f;
#pragma unroll
            for (int j = 0; j < UNIT; j++) {
                float v = r[c * UNIT + j];
                s += v * v;
            }
            if (s > best) { best = s; bidx = c; }
        }
        bi[threadIdx.x] = bidx;
    }
    __syncthreads();

    uint4* dst = (uint4*)(vj + (size_t)b0 * D_IN_PAD);
    for (int q = threadIdx.x; q < 64 * 24; q += 256) {
        int s = q / 24, j = q % 24;
        uint4 v = make_uint4(0u, 0u, 0u, 0u);
        int c = j >> 1;
        if (j < 20 && c == bi[s]) {
            const float* p = &xs[s * 168 + c * UNIT + (j & 1) * 8];
            __half2 h0 = __floats2half2_rn(p[0], p[1]);
            __half2 h1 = __floats2half2_rn(p[2], p[3]);
            __half2 h2 = __floats2half2_rn(p[4], p[5]);
            __half2 h3 = __floats2half2_rn(p[6], p[7]);
            v.x = *(uint32_t*)&h0; v.y = *(uint32_t*)&h1;
            v.z = *(uint32_t*)&h2; v.w = *(uint32_t*)&h3;
        }
        dst[q] = v;
    }
}

// ---------------- mma helpers ----------------
__device__ __forceinline__ void ldm_x4(uint32_t& r0, uint32_t& r1,
                                       uint32_t& r2, uint32_t& r3,
                                       uint32_t addr) {
    asm volatile("ldmatrix.sync.aligned.m8n8.x4.shared.b16 {%0,%1,%2,%3}, [%4];\n"
                 : "=r"(r0), "=r"(r1), "=r"(r2), "=r"(r3)
                 : "r"(addr));
}

__device__ __forceinline__ void ldm_x4_t(uint32_t& r0, uint32_t& r1,
                                         uint32_t& r2, uint32_t& r3,
                                         uint32_t addr) {
    asm volatile("ldmatrix.sync.aligned.m8n8.x4.trans.shared.b16 {%0,%1,%2,%3}, [%4];\n"
                 : "=r"(r0), "=r"(r1), "=r"(r2), "=r"(r3)
                 : "r"(addr));
}

__device__ __forceinline__ void mma_f16(uint32_t* c, const uint32_t* a,
                                        const uint32_t* b) {
    asm volatile(
        "mma.sync.aligned.m16n8k16.row.col.f16.f16.f16.f16 "
        "{%0,%1}, {%2,%3,%4,%5}, {%6,%7}, {%0,%1};\n"
        : "+r"(c[0]), "+r"(c[1])
        : "r"(a[0]), "r"(a[1]), "r"(a[2]), "r"(a[3]), "r"(b[0]), "r"(b[1]));
}

// ---------------- geometry: BM=128, BN=128, BK=64, 2 stages, 3 CTAs/SM ------
#define BK 64
#define A_LDS 72     // 64 + 8 (halves)
#define B_LDS 136    // 128 + 8 (halves)
#define STAGES 2
#define A_STG (128 * A_LDS)          // 9216 halves
#define B_STG (BK * B_LDS)           // 8704 halves
#define SMEM_BYTES (STAGES * (A_STG + B_STG) * 2)   // 71680 B

// A tile 128x64 (1024 x 16B -> 4/thr), B tile 64x128 (1024 x 16B -> 4/thr)
__device__ __forceinline__ void ld_stage(uint32_t sA, uint32_t sB,
                                         const __half* __restrict__ A,
                                         const __half* __restrict__ Bm,
                                         int bm, int bn, int K, int N, int t,
                                         int tid) {
    const __half* Ag = A + (size_t)bm * K + t * BK;
    const __half* Bg = Bm + (size_t)t * BK * N + bn;
#pragma unroll
    for (int i = 0; i < 4; i++) {
        int q = tid + i * 256;
        int ar = q >> 3, ac = (q & 7) * 8;
        asm volatile("cp.async.cg.shared.global [%0], [%1], 16;" ::
                     "r"(sA + (uint32_t)(ar * A_LDS + ac) * 2u),
                     "l"(Ag + (size_t)ar * K + ac));
        int br = q >> 4, bc = (q & 15) * 8;
        asm volatile("cp.async.cg.shared.global [%0], [%1], 16;" ::
                     "r"(sB + (uint32_t)(br * B_LDS + bc) * 2u),
                     "l"(Bg + (size_t)br * N + bc));
    }
    asm volatile("cp.async.commit_group;" ::: "memory");
}

// ================= GEMM: tile 128x128, warp tile 32x64, 3 CTAs/SM ==========
// 8 warps (4 warpM x 2 warpN). fp16 accumulation. 6 warps/SMSP.
template <int ACT>
__global__ __launch_bounds__(256, 3) void gemm_kernel(
    const __half* __restrict__ A,
    const __half* __restrict__ Bm,
    const float* __restrict__ bias,
    void* __restrict__ Cout,
    int N, int K) {
    extern __shared__ __half smem[];

    const int tid = threadIdx.x;
    const int warp = tid >> 5;
    const int lane = tid & 31;
    const int warpM = warp >> 1;   // 0..3, 32 rows each
    const int warpN = warp & 1;    // 0..1, 64 cols each
    const int bm = blockIdx.y * 128;
    const int bn = blockIdx.x * 128;

    const uint32_t sBase = (uint32_t)__cvta_generic_to_shared(smem);
    const uint32_t aBase = sBase;
    const uint32_t bBase = sBase + (uint32_t)STAGES * A_STG * 2u;

    const uint32_t aOffBase =
        (uint32_t)((warpM * 32 + (lane & 15)) * A_LDS + ((lane >> 4) << 3)) * 2u;
    const uint32_t bOffBase =
        (uint32_t)((lane & 15) * B_LDS + warpN * 64 + ((lane >> 4) << 3)) * 2u;

    uint32_t acc[2][8][2];
#pragma unroll
    for (int mt = 0; mt < 2; mt++)
#pragma unroll
        for (int n8 = 0; n8 < 8; n8++) {
            acc[mt][n8][0] = 0u;
            acc[mt][n8][1] = 0u;
        }

    const int T = K / BK;

    ld_stage(aBase, bBase, A, Bm, bm, bn, K, N, 0, tid);

    for (int t = 0; t < T; t++) {
        if (t + 1 < T) {
            int sl = (t + 1) & 1;
            ld_stage(aBase + (uint32_t)sl * A_STG * 2u,
                     bBase + (uint32_t)sl * B_STG * 2u,
                     A, Bm, bm, bn, K, N, t + 1, tid);
        } else {
            asm volatile("cp.async.commit_group;" ::: "memory");
        }
        asm volatile("cp.async.wait_group 1;" ::: "memory");
        __syncthreads();

        const int s = t & 1;
        const uint32_t sA = aBase + (uint32_t)s * A_STG * 2u + aOffBase;
        const uint32_t sB = bBase + (uint32_t)s * B_STG * 2u + bOffBase;

#pragma unroll
        for (int kk = 0; kk < 4; kk++) {
            uint32_t a[2][4];
#pragma unroll
            for (int mt = 0; mt < 2; mt++)
                ldm_x4(a[mt][0], a[mt][1], a[mt][2], a[mt][3],
                       sA + (uint32_t)(mt * 16 * A_LDS + kk * 16) * 2u);
            uint32_t b[8][2];
#pragma unroll
            for (int nt = 0; nt < 4; nt++) {
                uint32_t r0, r1, r2, r3;
                ldm_x4_t(r0, r1, r2, r3,
                         sB + (uint32_t)(kk * 16 * B_LDS + nt * 16) * 2u);
                b[2 * nt][0] = r0; b[2 * nt][1] = r1;
                b[2 * nt + 1][0] = r2; b[2 * nt + 1][1] = r3;
            }
#pragma unroll
            for (int mt = 0; mt < 2; mt++)
#pragma unroll
                for (int n8 = 0; n8 < 8; n8++)
                    mma_f16(acc[mt][n8], a[mt], b[n8]);
        }
        __syncthreads();
    }

    // epilogue
    const int lr = lane >> 2;
    const int lc = (lane & 3) * 2;
#pragma unroll
    for (int mt = 0; mt < 2; mt++) {
#pragma unroll
        for (int n8 = 0; n8 < 8; n8++) {
            int row0 = bm + warpM * 32 + mt * 16 + lr;
            int col = bn + warpN * 64 + n8 * 8 + lc;
            float bz0 = __ldg(bias + col);
            float bz1 = __ldg(bias + col + 1);
            float2 p0 = __half22float2(*(__half2*)&acc[mt][n8][0]);
            float2 p1 = __half22float2(*(__half2*)&acc[mt][n8][1]);
            float v00 = p0.x + bz0;
            float v01 = p0.y + bz1;
            float v10 = p1.x + bz0;
            float v11 = p1.y + bz1;
            if (ACT == 0) {
                v00 = fmaxf(v00, 0.f); v01 = fmaxf(v01, 0.f);
                v10 = fmaxf(v10, 0.f); v11 = fmaxf(v11, 0.f);
                __half* C = (__half*)Cout;
                *(__half2*)&C[(size_t)row0 * N + col] = __floats2half2_rn(v00, v01);
                *(__half2*)&C[(size_t)(row0 + 8) * N + col] = __floats2half2_rn(v10, v11);
            } else {
                v00 = 1.f / (1.f + __expf(-v00));
                v01 = 1.f / (1.f + __expf(-v01));
                v10 = 1.f / (1.f + __expf(-v10));
                v11 = 1.f / (1.f + __expf(-v11));
                float* C = (float*)Cout;
                *(float2*)&C[(size_t)row0 * N + col] = make_float2(v00, v01);
                *(float2*)&C[(size_t)(row0 + 8) * N + col] = make_float2(v10, v11);
            }
        }
    }
}

// ---------------- launch ----------------
extern "C" void kernel_launch(void* const* d_in, const int* in_sizes, int n_in,
                              void* d_out, int out_size) {
    const float* x  = (const float*)d_in[0];
    const float* W1 = (const float*)d_in[2];
    const float* b1 = (const float*)d_in[3];
    const float* W2 = (const float*)d_in[4];
    const float* b2 = (const float*)d_in[5];
    const float* W3 = (const float*)d_in[6];
    const float* b3 = (const float*)d_in[7];

    void *pvj, *ph1, *ph2, *pw1, *pw2, *pw3;
    cudaGetSymbolAddress(&pvj, g_vj);
    cudaGetSymbolAddress(&ph1, g_h1);
    cudaGetSymbolAddress(&ph2, g_h2);
    cudaGetSymbolAddress(&pw1, g_w1);
    cudaGetSymbolAddress(&pw2, g_w2);
    cudaGetSymbolAddress(&pw3, g_w3);
    __half* vj  = (__half*)pvj;
    __half* h1  = (__half*)ph1;
    __half* h2  = (__half*)ph2;
    __half* w1h = (__half*)pw1;
    __half* w2h = (__half*)pw2;
    __half* w3h = (__half*)pw3;

    cudaFuncSetAttribute(gemm_kernel<0>,
                         cudaFuncAttributeMaxDynamicSharedMemorySize, SMEM_BYTES);
    cudaFuncSetAttribute(gemm_kernel<1>,
                         cudaFuncAttributeMaxDynamicSharedMemorySize, SMEM_BYTES);

    f2h_all<<<592, 256>>>((const float2*)W1, (const float2*)W2,
                          (const float2*)W3, (__half2*)w1h,
                          (__half2*)w2h, (__half2*)w3h);

    mask_kernel<<<B_SAMPLES / 64, 256>>>(x, vj);

    gemm_kernel<0><<<dim3(H1_DIM / 128, B_SAMPLES / 128), 256, SMEM_BYTES>>>(
        vj, w1h, b1, h1, H1_DIM, D_IN_PAD);
    gemm_kernel<0><<<dim3(H2_DIM / 128, B_SAMPLES / 128), 256, SMEM_BYTES>>>(
        h1, w2h, b2, h2, H2_DIM, H1_DIM);
    gemm_kernel<1><<<dim3(O_DIM / 128, B_SAMPLES / 128), 256, SMEM_BYTES>>>(
        h2, w3h, b3, d_out, O_DIM, H2_DIM);
}